// round 2
// baseline (speedup 1.0000x reference)
#include <cuda_runtime.h>

// AdaptiveEmbedding: 3-cluster gather + projection.
//   0: emb_input  int  [8,2048]  (dtype int32 or int64 — detected at runtime)
//   1: emb0 f32 [20000,1024]   2: w0 f32 [1024,1024]
//   3: emb1 f32 [20000,256]    4: w1 f32 [1024,256]
//   5: emb2 f32 [10257,64]     6: w2 f32 [1024,64]
// output: f32 [8,2048,1024]

#define N_TOK 16384
#define VOCAB 50257
#define D_OUT 1024
#define TM 64
#define TN 64
#define BK 16
#define PAD 68   // smem row stride: float4-aligned, not multiple of 32

// Scratch (device allocations are forbidden).
__device__ int g_cnt[3];
__device__ int g_is64;
__device__ int g_tok[3 * N_TOK];
__device__ int g_loc[3 * N_TOK];

// Decide whether the index buffer is int64 or int32.
// Reads only the first 64KB (8192 int64) — in-bounds under either dtype.
// If the data is int32, int64-aliased reads are huge with overwhelming
// probability, so "all valid" => genuinely int64.
__global__ void detect_kernel(const long long* __restrict__ p) {
    __shared__ int bad;
    if (threadIdx.x == 0) bad = 0;
    __syncthreads();
    for (int i = threadIdx.x; i < 8192; i += blockDim.x) {
        long long v = p[i];
        if (v < 0 || v >= VOCAB) bad = 1;
    }
    __syncthreads();
    if (threadIdx.x == 0) {
        g_is64 = (bad == 0);
        g_cnt[0] = 0; g_cnt[1] = 0; g_cnt[2] = 0;
    }
}

__global__ void classify_kernel(const void* __restrict__ idx_raw) {
    int n = blockIdx.x * blockDim.x + threadIdx.x;
    if (n >= N_TOK) return;
    int v;
    if (g_is64) v = (int)((const long long*)idx_raw)[n];
    else        v = ((const int*)idx_raw)[n];
    v = min(max(v, 0), VOCAB - 1);                       // defensive clamp
    int c  = (v >= 40000) ? 2 : ((v >= 20000) ? 1 : 0);
    int lo = (c == 2) ? 40000 : ((c == 1) ? 20000 : 0);
    int hi = (c == 2) ? 10256 : 19999;                   // rows-1 per table
    int local = min(v - lo, hi);
    int p = atomicAdd(&g_cnt[c], 1);
    g_tok[c * N_TOK + p] = n;
    g_loc[c * N_TOK + p] = local;
}

// Tiled SGEMM, gathered A rows, scattered C rows.
// C[m, n] = sum_k emb[loc_m, k] * w[n, k]    (w is [D, h] row-major)
__global__ void __launch_bounds__(256, 4) gemm_kernel(
    const float* __restrict__ emb,
    const float* __restrict__ w,
    float* __restrict__ out,
    int cluster, int h)
{
    const int cnt = g_cnt[cluster];
    const int m0  = blockIdx.x * TM;
    if (m0 >= cnt) return;
    const int n0  = blockIdx.y * TN;

    __shared__ __align__(16) float As[BK][PAD];
    __shared__ __align__(16) float Bs[BK][PAD];
    __shared__ int s_tok[TM];
    __shared__ int s_loc[TM];

    const int t  = threadIdx.x;
    const int lk = t % BK;
    const int lm = t / BK;
    const int tx = t % 16;
    const int ty = t / 16;

    if (t < TM) {
        int m = m0 + t;
        if (m < cnt) {
            s_tok[t] = g_tok[cluster * N_TOK + m];
            s_loc[t] = g_loc[cluster * N_TOK + m];
        } else {
            s_tok[t] = -1;
            s_loc[t] = 0;
        }
    }
    __syncthreads();

    float acc[4][4];
#pragma unroll
    for (int i = 0; i < 4; i++)
#pragma unroll
        for (int j = 0; j < 4; j++) acc[i][j] = 0.0f;

    for (int k0 = 0; k0 < h; k0 += BK) {
#pragma unroll
        for (int r = 0; r < 4; r++) {
            int m = lm + r * 16;
            As[lk][m] = emb[(size_t)s_loc[m] * h + (k0 + lk)];
        }
#pragma unroll
        for (int r = 0; r < 4; r++) {
            int nn = lm + r * 16;
            Bs[lk][nn] = w[(size_t)(n0 + nn) * h + (k0 + lk)];
        }
        __syncthreads();

#pragma unroll
        for (int kk = 0; kk < BK; kk++) {
            float4 a = *(const float4*)&As[kk][ty * 4];
            float4 b = *(const float4*)&Bs[kk][tx * 4];
            float av[4] = {a.x, a.y, a.z, a.w};
            float bv[4] = {b.x, b.y, b.z, b.w};
#pragma unroll
            for (int i = 0; i < 4; i++)
#pragma unroll
                for (int j = 0; j < 4; j++)
                    acc[i][j] += av[i] * bv[j];
        }
        __syncthreads();
    }

#pragma unroll
    for (int i = 0; i < 4; i++) {
        int m = ty * 4 + i;
        int tok = s_tok[m];
        if (tok >= 0) {
            float4 v = make_float4(acc[i][0], acc[i][1], acc[i][2], acc[i][3]);
            *(float4*)&out[(size_t)tok * D_OUT + n0 + tx * 4] = v;
        }
    }
}

extern "C" void kernel_launch(void* const* d_in, const int* in_sizes, int n_in,
                              void* d_out, int out_size)
{
    const void*  idx  = d_in[0];
    const float* emb0 = (const float*)d_in[1];
    const float* w0   = (const float*)d_in[2];
    const float* emb1 = (const float*)d_in[3];
    const float* w1   = (const float*)d_in[4];
    const float* emb2 = (const float*)d_in[5];
    const float* w2   = (const float*)d_in[6];
    float* out = (float*)d_out;

    detect_kernel<<<1, 256>>>((const long long*)idx);
    classify_kernel<<<N_TOK / 256, 256>>>(idx);

    dim3 grid(N_TOK / TM, D_OUT / TN);  // worst-case M; surplus blocks exit early
    gemm_kernel<<<grid, 256>>>(emb0, w0, out, 0, 1024);
    gemm_kernel<<<grid, 256>>>(emb1, w1, out, 1, 256);
    gemm_kernel<<<grid, 256>>>(emb2, w2, out, 2, 64);
}

// round 5
// speedup vs baseline: 3.4715x; 3.4715x over previous
#include <cuda_runtime.h>
#include <cuda_bf16.h>
#include <cstdint>

// AdaptiveEmbedding: 3-cluster gather + projection via mma.sync bf16 (2-term split).
//   0: emb_input int32/int64 [8,2048] (runtime-detected)
//   1: emb0 f32 [20000,1024]   2: w0 f32 [1024,1024]
//   3: emb1 f32 [20000,256]    4: w1 f32 [1024,256]
//   5: emb2 f32 [10257,64]     6: w2 f32 [1024,64]
// out: f32 [8,2048,1024]
// NOTE: harness compiles PTX for baseline sm_103 (no 'a') => tcgen05 unavailable;
// use ldmatrix + mma.sync.m16n8k16 bf16 (PTX ISA 7.0 baseline).

#define N_TOK 16384
#define VOCAB 50257
#define D_OUT 1024

__device__ int g_cnt[3];
__device__ int g_is64;
__device__ int g_tok[3 * N_TOK];
__device__ int g_loc[3 * N_TOK];

// ---------------- routing ----------------
__global__ void detect_kernel(const long long* __restrict__ p) {
    __shared__ int bad;
    if (threadIdx.x == 0) bad = 0;
    __syncthreads();
    for (int i = threadIdx.x; i < 8192; i += blockDim.x) {
        long long v = p[i];
        if (v < 0 || v >= VOCAB) bad = 1;
    }
    __syncthreads();
    if (threadIdx.x == 0) {
        g_is64 = (bad == 0);
        g_cnt[0] = 0; g_cnt[1] = 0; g_cnt[2] = 0;
    }
}

__global__ void classify_kernel(const void* __restrict__ idx_raw) {
    int n = blockIdx.x * blockDim.x + threadIdx.x;
    if (n >= N_TOK) return;
    int v;
    if (g_is64) v = (int)((const long long*)idx_raw)[n];
    else        v = ((const int*)idx_raw)[n];
    v = min(max(v, 0), VOCAB - 1);
    int c  = (v >= 40000) ? 2 : ((v >= 20000) ? 1 : 0);
    int lo = (c == 2) ? 40000 : ((c == 1) ? 20000 : 0);
    int hi = (c == 2) ? 10256 : 19999;
    int local = min(v - lo, hi);
    int p = atomicAdd(&g_cnt[c], 1);
    g_tok[c * N_TOK + p] = n;
    g_loc[c * N_TOK + p] = local;
}

// ---------------- helpers ----------------
__device__ __forceinline__ uint32_t smem_u32(const void* p) {
    uint32_t a;
    asm("{ .reg .u64 t; cvta.to.shared.u64 t, %1; cvt.u32.u64 %0, t; }" : "=r"(a) : "l"(p));
    return a;
}
__device__ __forceinline__ uint32_t pack_bf16(float a, float b) {
    __nv_bfloat162 t = __floats2bfloat162_rn(a, b);
    return *(uint32_t*)&t;
}
__device__ __forceinline__ void ldsm4(uint32_t* r, uint32_t addr) {
    asm volatile("ldmatrix.sync.aligned.m8n8.x4.shared.b16 {%0,%1,%2,%3}, [%4];"
                 : "=r"(r[0]), "=r"(r[1]), "=r"(r[2]), "=r"(r[3]) : "r"(addr));
}
__device__ __forceinline__ void mma_bf16(float* c, const uint32_t* a, uint32_t b0, uint32_t b1) {
    asm volatile(
        "mma.sync.aligned.m16n8k16.row.col.f32.bf16.bf16.f32 "
        "{%0,%1,%2,%3}, {%4,%5,%6,%7}, {%8,%9}, {%0,%1,%2,%3};"
        : "+f"(c[0]), "+f"(c[1]), "+f"(c[2]), "+f"(c[3])
        : "r"(a[0]), "r"(a[1]), "r"(a[2]), "r"(a[3]), "r"(b0), "r"(b1));
}
// smem tile row = 128 B = 8 subs of 16B; subs 0-3 = hi(k0..31), 4-7 = lo(k0..31)
// XOR swizzle: sub ^= (row & 7)
__device__ __forceinline__ uint32_t sw_off(int row, int sub) {
    return (uint32_t)(row * 128 + ((sub ^ (row & 7)) << 4));
}

// ---------------- GEMM ----------------
// C[m,n] = sum_k emb[loc_m,k] * w[n,k];  CTA 128x128, 8 warps (4M x 2N), warp 32x64
__global__ void __launch_bounds__(256) gemm_mma(
    const float* __restrict__ emb,
    const float* __restrict__ w,
    float* __restrict__ out,
    int cluster, int h)
{
    const int cnt = g_cnt[cluster];
    const int m0  = blockIdx.x * 128;
    if (m0 >= cnt) return;
    const int n0  = blockIdx.y * 128;

    __shared__ int s_tok[128];
    __shared__ int s_loc[128];
    __shared__ __align__(16) char sA[128 * 128];
    __shared__ __align__(16) char sB[128 * 128];

    const int t    = threadIdx.x;
    const int lane = t & 31;
    const int wid  = t >> 5;
    const int wm   = wid & 3;          // M block of 32
    const int wn   = wid >> 2;         // N block of 64

    if (t < 128) {
        int m = m0 + t;
        if (m < cnt) {
            s_tok[t] = g_tok[cluster * N_TOK + m];
            s_loc[t] = g_loc[cluster * N_TOK + m];
        } else { s_tok[t] = -1; s_loc[t] = 0; }
    }
    __syncthreads();

    const uint32_t sbA = smem_u32(sA);
    const uint32_t sbB = smem_u32(sB);

    float acc[2][8][4];
#pragma unroll
    for (int i = 0; i < 2; i++)
#pragma unroll
        for (int j = 0; j < 8; j++)
#pragma unroll
            for (int q = 0; q < 4; q++) acc[i][j][q] = 0.0f;

    // ldmatrix lane roles
    const int li  = lane & 7;
    const int sel = lane >> 3;

    const int r_stage = t >> 2;        // 0..63 (two rows per thread: r, r+64)
    const int q_stage = t & 3;         // 8-f32 chunk within the 32-wide K stage

    const int nkt = h >> 5;
    for (int kt = 0; kt < nkt; kt++) {
        if (kt) __syncthreads();       // smem reuse fence
        const int k0 = kt * 32;
        // stage A (gathered tokens) and B (weight rows), split hi/lo
#pragma unroll
        for (int half = 0; half < 2; half++) {
            int r = r_stage + half * 64;
            {
                const float* src = emb + (size_t)s_loc[r] * h + k0 + q_stage * 8;
                float4 v0 = *(const float4*)src;
                float4 v1 = *(const float4*)(src + 4);
                float f[8] = {v0.x, v0.y, v0.z, v0.w, v1.x, v1.y, v1.z, v1.w};
                float hf[8], lf[8];
#pragma unroll
                for (int e = 0; e < 8; e++) {
                    hf[e] = __bfloat162float(__float2bfloat16(f[e]));
                    lf[e] = f[e] - hf[e];
                }
                uint4 hv = make_uint4(pack_bf16(hf[0], hf[1]), pack_bf16(hf[2], hf[3]),
                                      pack_bf16(hf[4], hf[5]), pack_bf16(hf[6], hf[7]));
                uint4 lv = make_uint4(pack_bf16(lf[0], lf[1]), pack_bf16(lf[2], lf[3]),
                                      pack_bf16(lf[4], lf[5]), pack_bf16(lf[6], lf[7]));
                *(uint4*)(sA + sw_off(r, q_stage))     = hv;
                *(uint4*)(sA + sw_off(r, 4 + q_stage)) = lv;
            }
            {
                const float* src = w + (size_t)(n0 + r) * h + k0 + q_stage * 8;
                float4 v0 = *(const float4*)src;
                float4 v1 = *(const float4*)(src + 4);
                float f[8] = {v0.x, v0.y, v0.z, v0.w, v1.x, v1.y, v1.z, v1.w};
                float hf[8], lf[8];
#pragma unroll
                for (int e = 0; e < 8; e++) {
                    hf[e] = __bfloat162float(__float2bfloat16(f[e]));
                    lf[e] = f[e] - hf[e];
                }
                uint4 hv = make_uint4(pack_bf16(hf[0], hf[1]), pack_bf16(hf[2], hf[3]),
                                      pack_bf16(hf[4], hf[5]), pack_bf16(hf[6], hf[7]));
                uint4 lv = make_uint4(pack_bf16(lf[0], lf[1]), pack_bf16(lf[2], lf[3]),
                                      pack_bf16(lf[4], lf[5]), pack_bf16(lf[6], lf[7]));
                *(uint4*)(sB + sw_off(r, q_stage))     = hv;
                *(uint4*)(sB + sw_off(r, 4 + q_stage)) = lv;
            }
        }
        __syncthreads();

#pragma unroll
        for (int kh = 0; kh < 2; kh++) {
            const int shi = 2 * kh;          // hi subs {shi, shi+1}
            const int slo = 4 + 2 * kh;      // lo subs
            uint32_t ahi[2][4], alo[2][4];
#pragma unroll
            for (int m = 0; m < 2; m++) {
                int row = wm * 32 + m * 16 + li + ((sel & 1) ? 8 : 0);
                int subh = shi + ((sel >> 1) & 1);
                int subl = slo + ((sel >> 1) & 1);
                ldsm4(ahi[m], sbA + sw_off(row, subh));
                ldsm4(alo[m], sbA + sw_off(row, subl));
            }
#pragma unroll
            for (int p = 0; p < 4; p++) {
                int nb = wn * 64 + p * 16;
                uint32_t bh[4], bl[4];
                int brow = nb + li + ((sel >> 1) ? 8 : 0);
                int bsh  = shi + (sel & 1);
                int bsl  = slo + (sel & 1);
                ldsm4(bh, sbB + sw_off(brow, bsh));
                ldsm4(bl, sbB + sw_off(brow, bsl));
#pragma unroll
                for (int m = 0; m < 2; m++) {
                    mma_bf16(acc[m][2 * p],     ahi[m], bh[0], bh[1]);
                    mma_bf16(acc[m][2 * p],     ahi[m], bl[0], bl[1]);
                    mma_bf16(acc[m][2 * p],     alo[m], bh[0], bh[1]);
                    mma_bf16(acc[m][2 * p + 1], ahi[m], bh[2], bh[3]);
                    mma_bf16(acc[m][2 * p + 1], ahi[m], bl[2], bl[3]);
                    mma_bf16(acc[m][2 * p + 1], alo[m], bh[2], bh[3]);
                }
            }
        }
    }

    // epilogue: scatter accumulators to token rows
    const int g  = lane >> 2;
    const int tq = lane & 3;
#pragma unroll
    for (int m = 0; m < 2; m++) {
        int r0 = wm * 32 + m * 16 + g;
        int tokA = s_tok[r0];
        int tokB = s_tok[r0 + 8];
#pragma unroll
        for (int jj = 0; jj < 8; jj++) {
            int col = n0 + wn * 64 + jj * 8 + tq * 2;
            if (tokA >= 0)
                *(float2*)&out[(size_t)tokA * D_OUT + col] = make_float2(acc[m][jj][0], acc[m][jj][1]);
            if (tokB >= 0)
                *(float2*)&out[(size_t)tokB * D_OUT + col] = make_float2(acc[m][jj][2], acc[m][jj][3]);
        }
    }
}

extern "C" void kernel_launch(void* const* d_in, const int* in_sizes, int n_in,
                              void* d_out, int out_size)
{
    const void*  idx  = d_in[0];
    const float* emb0 = (const float*)d_in[1];
    const float* w0   = (const float*)d_in[2];
    const float* emb1 = (const float*)d_in[3];
    const float* w1   = (const float*)d_in[4];
    const float* emb2 = (const float*)d_in[5];
    const float* w2   = (const float*)d_in[6];
    float* out = (float*)d_out;

    detect_kernel<<<1, 256>>>((const long long*)idx);
    classify_kernel<<<N_TOK / 256, 256>>>(idx);

    dim3 grid(N_TOK / 128, D_OUT / 128);   // worst-case M; surplus CTAs exit early
    gemm_mma<<<grid, 256>>>(emb0, w0, out, 0, 1024);
    gemm_mma<<<grid, 256>>>(emb1, w1, out, 1, 256);
    gemm_mma<<<grid, 256>>>(emb2, w2, out, 2, 64);
}

// round 6
// speedup vs baseline: 3.7967x; 1.0937x over previous
#include <cuda_runtime.h>
#include <cuda_bf16.h>
#include <cstdint>

// AdaptiveEmbedding: 3-cluster gather+projection.
// Pipeline: detect dtype -> classify (warp-aggregated) -> pre-split emb rows &
// weights into bf16 hi/lo scratch -> cp.async double-buffered mma.sync GEMM.
// Baseline-PTX only (harness targets sm_103, no 'a': no tcgen05).

#define N_TOK 16384
#define VOCAB 50257
#define D_OUT 1024
#define TM 256
#define TN 128
#define TK 32

// ---------------- scratch (no allocations allowed) ----------------
__device__ int g_cnt[3];
__device__ int g_is64;
__device__ int g_tok[3 * N_TOK];
__device__ int g_loc[3 * N_TOK];
// A scratch: worst-case 16384 rows per cluster. bases: c0=0, c1=16384*1024, c2=+16384*256
#define A_ELEMS (16384 * 1344)
#define AB1 (16384 * 1024)
#define AB2 (16384 * 1280)
__device__ __nv_bfloat16 g_Ahi[A_ELEMS];
__device__ __nv_bfloat16 g_Alo[A_ELEMS];
// W scratch: 1024 rows per cluster of h cols. bases: 0, 1024*1024, +1024*256
#define W_ELEMS (1024 * 1344)
#define WB1 (1024 * 1024)
#define WB2 (1024 * 1280)
__device__ __nv_bfloat16 g_Whi[W_ELEMS];
__device__ __nv_bfloat16 g_Wlo[W_ELEMS];

// ---------------- helpers ----------------
__device__ __forceinline__ uint32_t smem_u32(const void* p) {
    uint32_t a;
    asm("{ .reg .u64 t; cvta.to.shared.u64 t, %1; cvt.u32.u64 %0, t; }" : "=r"(a) : "l"(p));
    return a;
}
__device__ __forceinline__ void ldsm4(uint32_t* r, uint32_t addr) {
    asm volatile("ldmatrix.sync.aligned.m8n8.x4.shared.b16 {%0,%1,%2,%3}, [%4];"
                 : "=r"(r[0]), "=r"(r[1]), "=r"(r[2]), "=r"(r[3]) : "r"(addr));
}
__device__ __forceinline__ void mma_bf16(float* c, const uint32_t* a, uint32_t b0, uint32_t b1) {
    asm volatile(
        "mma.sync.aligned.m16n8k16.row.col.f32.bf16.bf16.f32 "
        "{%0,%1,%2,%3}, {%4,%5,%6,%7}, {%8,%9}, {%0,%1,%2,%3};"
        : "+f"(c[0]), "+f"(c[1]), "+f"(c[2]), "+f"(c[3])
        : "r"(a[0]), "r"(a[1]), "r"(a[2]), "r"(a[3]), "r"(b0), "r"(b1));
}
__device__ __forceinline__ void cp16(uint32_t dst, const void* src) {
    asm volatile("cp.async.cg.shared.global [%0], [%1], 16;" :: "r"(dst), "l"(src));
}
#define CP_COMMIT() asm volatile("cp.async.commit_group;" ::: "memory")
#define CP_WAIT1()  asm volatile("cp.async.wait_group 1;" ::: "memory")

// smem tile row = 128B = 8 subs of 16B; subs 0-3 = hi(k0..31), 4-7 = lo.
// XOR swizzle: sub ^= (row & 7)
__device__ __forceinline__ uint32_t sw_off(int row, int sub) {
    return (uint32_t)(row * 128 + ((sub ^ (row & 7)) << 4));
}

// ---------------- routing ----------------
__global__ void detect_kernel(const long long* __restrict__ p) {
    __shared__ int bad;
    if (threadIdx.x == 0) bad = 0;
    __syncthreads();
    for (int i = threadIdx.x; i < 8192; i += blockDim.x) {
        long long v = p[i];
        if (v < 0 || v >= VOCAB) bad = 1;
    }
    __syncthreads();
    if (threadIdx.x == 0) {
        g_is64 = (bad == 0);
        g_cnt[0] = 0; g_cnt[1] = 0; g_cnt[2] = 0;
    }
}

__global__ void classify_kernel(const void* __restrict__ idx_raw) {
    int n = blockIdx.x * blockDim.x + threadIdx.x;
    if (n >= N_TOK) return;
    int lane = threadIdx.x & 31;
    int v;
    if (g_is64) v = (int)((const long long*)idx_raw)[n];
    else        v = ((const int*)idx_raw)[n];
    v = min(max(v, 0), VOCAB - 1);
    int c  = (v >= 40000) ? 2 : ((v >= 20000) ? 1 : 0);
    int lo = (c == 2) ? 40000 : ((c == 1) ? 20000 : 0);
    int hicap = (c == 2) ? 10256 : 19999;
    int local = min(v - lo, hicap);
#pragma unroll
    for (int cc = 0; cc < 3; cc++) {
        unsigned m = __ballot_sync(0xFFFFFFFFu, c == cc);
        if (c == cc) {
            int leader = __ffs(m) - 1;
            int base = 0;
            if (lane == leader) base = atomicAdd(&g_cnt[cc], __popc(m));
            base = __shfl_sync(m, base, leader);
            int pos = base + __popc(m & ((1u << lane) - 1u));
            g_tok[cc * N_TOK + pos] = n;
            g_loc[cc * N_TOK + pos] = local;
        }
    }
}

// ---------------- pre-split converters ----------------
__device__ __forceinline__ void split8(const float* src, uint4& hv, uint4& lv) {
    float4 v0 = *(const float4*)src;
    float4 v1 = *(const float4*)(src + 4);
    float f[8] = {v0.x, v0.y, v0.z, v0.w, v1.x, v1.y, v1.z, v1.w};
    __nv_bfloat16 hb[8], lb[8];
#pragma unroll
    for (int e = 0; e < 8; e++) {
        hb[e] = __float2bfloat16(f[e]);
        lb[e] = __float2bfloat16(f[e] - __bfloat162float(hb[e]));
    }
    __nv_bfloat162 h01 = __halves2bfloat162(hb[0], hb[1]);
    __nv_bfloat162 h23 = __halves2bfloat162(hb[2], hb[3]);
    __nv_bfloat162 h45 = __halves2bfloat162(hb[4], hb[5]);
    __nv_bfloat162 h67 = __halves2bfloat162(hb[6], hb[7]);
    __nv_bfloat162 l01 = __halves2bfloat162(lb[0], lb[1]);
    __nv_bfloat162 l23 = __halves2bfloat162(lb[2], lb[3]);
    __nv_bfloat162 l45 = __halves2bfloat162(lb[4], lb[5]);
    __nv_bfloat162 l67 = __halves2bfloat162(lb[6], lb[7]);
    hv = make_uint4(*(uint32_t*)&h01, *(uint32_t*)&h23, *(uint32_t*)&h45, *(uint32_t*)&h67);
    lv = make_uint4(*(uint32_t*)&l01, *(uint32_t*)&l23, *(uint32_t*)&l45, *(uint32_t*)&l67);
}

// gathered token rows -> compacted hi/lo bf16 rows
__global__ void conv_a(const float* __restrict__ emb, int cluster, int h, size_t baseA) {
    int cpr = h >> 3;
    int id = blockIdx.x * 256 + threadIdx.x;
    int s = id / cpr;
    if (s >= g_cnt[cluster]) return;
    int off = (id - s * cpr) * 8;
    const float* src = emb + (size_t)g_loc[cluster * N_TOK + s] * h + off;
    uint4 hv, lv;
    split8(src, hv, lv);
    size_t d = baseA + (size_t)s * h + off;
    *(uint4*)&g_Ahi[d] = hv;
    *(uint4*)&g_Alo[d] = lv;
}

// weight rows -> hi/lo bf16
__global__ void conv_w(const float* __restrict__ w, int h, size_t baseW) {
    int cpr = h >> 3;
    int id = blockIdx.x * 256 + threadIdx.x;
    int s = id / cpr;
    if (s >= D_OUT) return;
    int off = (id - s * cpr) * 8;
    uint4 hv, lv;
    split8(w + (size_t)s * h + off, hv, lv);
    size_t d = baseW + (size_t)s * h + off;
    *(uint4*)&g_Whi[d] = hv;
    *(uint4*)&g_Wlo[d] = lv;
}

// ---------------- GEMM ----------------
// smem layout (dynamic):
#define SM_TOK 0
#define SM_A0  1024
#define SM_A1  (SM_A0 + 32768)
#define SM_B0  (SM_A1 + 32768)
#define SM_B1  (SM_B0 + 16384)
#define SM_TOTAL (SM_B1 + 16384)

__device__ __forceinline__ void stage_tiles(
    uint32_t sA, uint32_t sB, int t,
    size_t baseA, size_t baseW, int m0, int n0, int k0, int h)
{
    // A: TM(256) rows x 128B = 2048 x 16B chunks, 512 threads -> 4 each
#pragma unroll
    for (int i = 0; i < 4; i++) {
        int cid = t + i * 512;
        int row = cid >> 3, sub = cid & 7;
        const __nv_bfloat16* src = (sub < 4 ? g_Ahi : g_Alo) +
            baseA + (size_t)(m0 + row) * h + k0 + (sub & 3) * 8;
        cp16(sA + sw_off(row, sub), src);
    }
    // B: TN(128) rows x 128B = 1024 chunks -> 2 each
#pragma unroll
    for (int i = 0; i < 2; i++) {
        int cid = t + i * 512;
        int row = cid >> 3, sub = cid & 7;
        const __nv_bfloat16* src = (sub < 4 ? g_Whi : g_Wlo) +
            baseW + (size_t)(n0 + row) * h + k0 + (sub & 3) * 8;
        cp16(sB + sw_off(row, sub), src);
    }
}

__global__ void __launch_bounds__(512, 1) gemm_mma(
    float* __restrict__ out, int cluster, int h, size_t baseA, size_t baseW)
{
    const int cnt = g_cnt[cluster];
    const int m0  = blockIdx.x * TM;
    if (m0 >= cnt) return;
    const int n0  = blockIdx.y * TN;

    extern __shared__ __align__(16) char smem[];
    const uint32_t sb = smem_u32(smem);
    int* s_tok = (int*)(smem + SM_TOK);

    const int t    = threadIdx.x;
    const int lane = t & 31;
    const int wid  = t >> 5;
    const int wm   = wid & 3;       // 4 M groups of 64 rows
    const int wn   = wid >> 2;      // 4 N groups of 32 cols
    const int li   = lane & 7;
    const int sel  = lane >> 3;

    if (t < TM) {
        int m = m0 + t;
        s_tok[t] = (m < cnt) ? g_tok[cluster * N_TOK + m] : -1;
    }

    const int nkt = h / TK;
    // prologue: stages 0 and 1
    stage_tiles(sb + SM_A0, sb + SM_B0, t, baseA, baseW, m0, n0, 0, h);
    CP_COMMIT();
    if (nkt > 1) stage_tiles(sb + SM_A1, sb + SM_B1, t, baseA, baseW, m0, n0, TK, h);
    CP_COMMIT();

    float acc[4][4][4];
#pragma unroll
    for (int i = 0; i < 4; i++)
#pragma unroll
        for (int j = 0; j < 4; j++)
#pragma unroll
            for (int q = 0; q < 4; q++) acc[i][j][q] = 0.0f;

    for (int kt = 0; kt < nkt; kt++) {
        CP_WAIT1();
        __syncthreads();
        const uint32_t bA = sb + (((kt & 1) == 0) ? SM_A0 : SM_A1);
        const uint32_t bB = sb + (((kt & 1) == 0) ? SM_B0 : SM_B1);
#pragma unroll
        for (int kh = 0; kh < 2; kh++) {
            const int sh = 2 * kh;
            const int sl = 4 + 2 * kh;
            uint32_t ah[4][4], al[4][4];
#pragma unroll
            for (int mf = 0; mf < 4; mf++) {
                int row = wm * 64 + mf * 16 + li + ((sel & 1) ? 8 : 0);
                ldsm4(ah[mf], bA + sw_off(row, sh + ((sel >> 1) & 1)));
                ldsm4(al[mf], bA + sw_off(row, sl + ((sel >> 1) & 1)));
            }
#pragma unroll
            for (int pp = 0; pp < 2; pp++) {
                int brow = wn * 32 + pp * 16 + li + ((sel >> 1) ? 8 : 0);
                uint32_t bh[4], bl[4];
                ldsm4(bh, bB + sw_off(brow, sh + (sel & 1)));
                ldsm4(bl, bB + sw_off(brow, sl + (sel & 1)));
#pragma unroll
                for (int mf = 0; mf < 4; mf++) {
                    mma_bf16(acc[mf][2 * pp],     ah[mf], bh[0], bh[1]);
                    mma_bf16(acc[mf][2 * pp],     ah[mf], bl[0], bl[1]);
                    mma_bf16(acc[mf][2 * pp],     al[mf], bh[0], bh[1]);
                    mma_bf16(acc[mf][2 * pp + 1], ah[mf], bh[2], bh[3]);
                    mma_bf16(acc[mf][2 * pp + 1], ah[mf], bl[2], bl[3]);
                    mma_bf16(acc[mf][2 * pp + 1], al[mf], bh[2], bh[3]);
                }
            }
        }
        __syncthreads();
        if (kt + 2 < nkt) {
            stage_tiles(bA, bB, t, baseA, baseW, m0, n0, (kt + 2) * TK, h);
        }
        CP_COMMIT();
    }

    // epilogue: scatter to token rows
    const int g  = lane >> 2;
    const int tq = lane & 3;
#pragma unroll
    for (int mf = 0; mf < 4; mf++) {
        int r0 = wm * 64 + mf * 16 + g;
        int tokA = s_tok[r0];
        int tokB = s_tok[r0 + 8];
#pragma unroll
        for (int nf = 0; nf < 4; nf++) {
            int col = n0 + wn * 32 + nf * 8 + tq * 2;
            if (tokA >= 0)
                *(float2*)&out[(size_t)tokA * D_OUT + col] =
                    make_float2(acc[mf][nf][0], acc[mf][nf][1]);
            if (tokB >= 0)
                *(float2*)&out[(size_t)tokB * D_OUT + col] =
                    make_float2(acc[mf][nf][2], acc[mf][nf][3]);
        }
    }
}

extern "C" void kernel_launch(void* const* d_in, const int* in_sizes, int n_in,
                              void* d_out, int out_size)
{
    const void*  idx  = d_in[0];
    const float* emb0 = (const float*)d_in[1];
    const float* w0   = (const float*)d_in[2];
    const float* emb1 = (const float*)d_in[3];
    const float* w1   = (const float*)d_in[4];
    const float* emb2 = (const float*)d_in[5];
    const float* w2   = (const float*)d_in[6];
    float* out = (float*)d_out;

    cudaFuncSetAttribute(gemm_mma, cudaFuncAttributeMaxDynamicSharedMemorySize, SM_TOTAL);

    detect_kernel<<<1, 256>>>((const long long*)idx);
    classify_kernel<<<N_TOK / 256, 256>>>(idx);

    conv_w<<<(D_OUT * 1024 / 8) / 256, 256>>>(w0, 1024, 0);
    conv_w<<<(D_OUT * 256 / 8) / 256, 256>>>(w1, 256, WB1);
    conv_w<<<(D_OUT * 64 / 8) / 256, 256>>>(w2, 64, WB2);

    conv_a<<<(N_TOK * 1024 / 8) / 256, 256>>>(emb0, 0, 1024, 0);
    conv_a<<<(N_TOK * 256 / 8) / 256, 256>>>(emb1, 1, 256, AB1);
    conv_a<<<(N_TOK * 64 / 8) / 256, 256>>>(emb2, 2, 64, AB2);

    dim3 grid(N_TOK / TM, D_OUT / TN);   // worst-case M; surplus CTAs exit early
    gemm_mma<<<grid, 512, SM_TOTAL>>>(out, 0, 1024, 0, 0);
    gemm_mma<<<grid, 512, SM_TOTAL>>>(out, 1, 256, AB1, WB1);
    gemm_mma<<<grid, 512, SM_TOTAL>>>(out, 2, 64, AB2, WB2);
}

// round 7
// speedup vs baseline: 4.7857x; 1.2605x over previous
#include <cuda_runtime.h>
#include <cuda_bf16.h>
#include <cstdint>

// AdaptiveEmbedding: 3-cluster gather+projection.
// detect dtype -> classify (warp-aggregated) -> fused pre-split (bf16 hi/lo)
// -> single fused cp.async double-buffered mma.sync GEMM over all clusters.
// Baseline-PTX only (harness targets sm_103, no 'a': no tcgen05).

#define N_TOK 16384
#define VOCAB 50257
#define D_OUT 1024
#define TM 256
#define TN 128
#define TK 32

// ---------------- scratch (no allocations allowed) ----------------
__device__ int g_cnt[3];
__device__ int g_is64;
__device__ int g_tok[3 * N_TOK];
__device__ int g_loc[3 * N_TOK];
#define A_ELEMS (16384 * 1344)
#define AB1 ((size_t)16384 * 1024)
#define AB2 ((size_t)16384 * 1280)
__device__ __nv_bfloat16 g_Ahi[A_ELEMS];
__device__ __nv_bfloat16 g_Alo[A_ELEMS];
#define W_ELEMS (1024 * 1344)
#define WB1 ((size_t)1024 * 1024)
#define WB2 ((size_t)1024 * 1280)
__device__ __nv_bfloat16 g_Whi[W_ELEMS];
__device__ __nv_bfloat16 g_Wlo[W_ELEMS];

__constant__ int   c_h[3]     = {1024, 256, 64};
__constant__ size_t c_baseA[3] = {0, AB1, AB2};
__constant__ size_t c_baseW[3] = {0, WB1, WB2};

// ---------------- helpers ----------------
__device__ __forceinline__ uint32_t smem_u32(const void* p) {
    uint32_t a;
    asm("{ .reg .u64 t; cvta.to.shared.u64 t, %1; cvt.u32.u64 %0, t; }" : "=r"(a) : "l"(p));
    return a;
}
__device__ __forceinline__ void ldsm4(uint32_t* r, uint32_t addr) {
    asm volatile("ldmatrix.sync.aligned.m8n8.x4.shared.b16 {%0,%1,%2,%3}, [%4];"
                 : "=r"(r[0]), "=r"(r[1]), "=r"(r[2]), "=r"(r[3]) : "r"(addr));
}
__device__ __forceinline__ void mma_bf16(float* c, const uint32_t* a, uint32_t b0, uint32_t b1) {
    asm volatile(
        "mma.sync.aligned.m16n8k16.row.col.f32.bf16.bf16.f32 "
        "{%0,%1,%2,%3}, {%4,%5,%6,%7}, {%8,%9}, {%0,%1,%2,%3};"
        : "+f"(c[0]), "+f"(c[1]), "+f"(c[2]), "+f"(c[3])
        : "r"(a[0]), "r"(a[1]), "r"(a[2]), "r"(a[3]), "r"(b0), "r"(b1));
}
__device__ __forceinline__ void cp16(uint32_t dst, const void* src) {
    asm volatile("cp.async.cg.shared.global [%0], [%1], 16;" :: "r"(dst), "l"(src));
}
#define CP_COMMIT() asm volatile("cp.async.commit_group;" ::: "memory")
#define CP_WAIT1()  asm volatile("cp.async.wait_group 1;" ::: "memory")

// smem tile row = 128B = 8 subs of 16B; subs 0-3 = hi(k0..31), 4-7 = lo.
__device__ __forceinline__ uint32_t sw_off(int row, int sub) {
    return (uint32_t)(row * 128 + ((sub ^ (row & 7)) << 4));
}

// ---------------- routing ----------------
__global__ void detect_kernel(const long long* __restrict__ p) {
    __shared__ int bad;
    if (threadIdx.x == 0) bad = 0;
    __syncthreads();
    for (int i = threadIdx.x; i < 8192; i += blockDim.x) {
        long long v = p[i];
        if (v < 0 || v >= VOCAB) bad = 1;
    }
    __syncthreads();
    if (threadIdx.x == 0) {
        g_is64 = (bad == 0);
        g_cnt[0] = 0; g_cnt[1] = 0; g_cnt[2] = 0;
    }
}

__global__ void classify_kernel(const void* __restrict__ idx_raw) {
    int n = blockIdx.x * blockDim.x + threadIdx.x;
    if (n >= N_TOK) return;
    int lane = threadIdx.x & 31;
    int v;
    if (g_is64) v = (int)((const long long*)idx_raw)[n];
    else        v = ((const int*)idx_raw)[n];
    v = min(max(v, 0), VOCAB - 1);
    int c  = (v >= 40000) ? 2 : ((v >= 20000) ? 1 : 0);
    int lo = (c == 2) ? 40000 : ((c == 1) ? 20000 : 0);
    int hicap = (c == 2) ? 10256 : 19999;
    int local = min(v - lo, hicap);
#pragma unroll
    for (int cc = 0; cc < 3; cc++) {
        unsigned m = __ballot_sync(0xFFFFFFFFu, c == cc);
        if (c == cc) {
            int leader = __ffs(m) - 1;
            int base = 0;
            if (lane == leader) base = atomicAdd(&g_cnt[cc], __popc(m));
            base = __shfl_sync(m, base, leader);
            int pos = base + __popc(m & ((1u << lane) - 1u));
            g_tok[cc * N_TOK + pos] = n;
            g_loc[cc * N_TOK + pos] = local;
        }
    }
}

// ---------------- pre-split converters (fused over clusters via z) ----------------
__device__ __forceinline__ void split8(const float* src, uint4& hv, uint4& lv) {
    float4 v0 = *(const float4*)src;
    float4 v1 = *(const float4*)(src + 4);
    float f[8] = {v0.x, v0.y, v0.z, v0.w, v1.x, v1.y, v1.z, v1.w};
    __nv_bfloat16 hb[8], lb[8];
#pragma unroll
    for (int e = 0; e < 8; e++) {
        hb[e] = __float2bfloat16(f[e]);
        lb[e] = __float2bfloat16(f[e] - __bfloat162float(hb[e]));
    }
    __nv_bfloat162 h01 = __halves2bfloat162(hb[0], hb[1]);
    __nv_bfloat162 h23 = __halves2bfloat162(hb[2], hb[3]);
    __nv_bfloat162 h45 = __halves2bfloat162(hb[4], hb[5]);
    __nv_bfloat162 h67 = __halves2bfloat162(hb[6], hb[7]);
    __nv_bfloat162 l01 = __halves2bfloat162(lb[0], lb[1]);
    __nv_bfloat162 l23 = __halves2bfloat162(lb[2], lb[3]);
    __nv_bfloat162 l45 = __halves2bfloat162(lb[4], lb[5]);
    __nv_bfloat162 l67 = __halves2bfloat162(lb[6], lb[7]);
    hv = make_uint4(*(uint32_t*)&h01, *(uint32_t*)&h23, *(uint32_t*)&h45, *(uint32_t*)&h67);
    lv = make_uint4(*(uint32_t*)&l01, *(uint32_t*)&l23, *(uint32_t*)&l45, *(uint32_t*)&l67);
}

__global__ void conv_a(const float* __restrict__ e0, const float* __restrict__ e1,
                       const float* __restrict__ e2) {
    const int cl = blockIdx.z;
    const int h = c_h[cl];
    const float* emb = (cl == 0) ? e0 : (cl == 1) ? e1 : e2;
    int cpr = h >> 3;
    int id = blockIdx.x * 256 + threadIdx.x;
    int s = id / cpr;
    if (s >= g_cnt[cl]) return;
    int off = (id - s * cpr) * 8;
    uint4 hv, lv;
    split8(emb + (size_t)g_loc[cl * N_TOK + s] * h + off, hv, lv);
    size_t d = c_baseA[cl] + (size_t)s * h + off;
    *(uint4*)&g_Ahi[d] = hv;
    *(uint4*)&g_Alo[d] = lv;
}

__global__ void conv_w(const float* __restrict__ w0, const float* __restrict__ w1,
                       const float* __restrict__ w2) {
    const int cl = blockIdx.z;
    const int h = c_h[cl];
    const float* w = (cl == 0) ? w0 : (cl == 1) ? w1 : w2;
    int cpr = h >> 3;
    int id = blockIdx.x * 256 + threadIdx.x;
    int s = id / cpr;
    if (s >= D_OUT) return;
    int off = (id - s * cpr) * 8;
    uint4 hv, lv;
    split8(w + (size_t)s * h + off, hv, lv);
    size_t d = c_baseW[cl] + (size_t)s * h + off;
    *(uint4*)&g_Whi[d] = hv;
    *(uint4*)&g_Wlo[d] = lv;
}

// ---------------- fused GEMM ----------------
#define SM_TOK 0
#define SM_A0  1024
#define SM_A1  (SM_A0 + 32768)
#define SM_B0  (SM_A1 + 32768)
#define SM_B1  (SM_B0 + 16384)
#define SM_TOTAL (SM_B1 + 16384)

__device__ __forceinline__ void stage_tiles(
    uint32_t sA, uint32_t sB, int t,
    size_t baseA, size_t baseW, int m0, int n0, int k0, int h)
{
#pragma unroll
    for (int i = 0; i < 4; i++) {
        int cid = t + i * 512;
        int row = cid >> 3, sub = cid & 7;
        const __nv_bfloat16* src = (sub < 4 ? g_Ahi : g_Alo) +
            baseA + (size_t)(m0 + row) * h + k0 + (sub & 3) * 8;
        cp16(sA + sw_off(row, sub), src);
    }
#pragma unroll
    for (int i = 0; i < 2; i++) {
        int cid = t + i * 512;
        int row = cid >> 3, sub = cid & 7;
        const __nv_bfloat16* src = (sub < 4 ? g_Whi : g_Wlo) +
            baseW + (size_t)(n0 + row) * h + k0 + (sub & 3) * 8;
        cp16(sB + sw_off(row, sub), src);
    }
}

__global__ void __launch_bounds__(512, 1) gemm_mma(float* __restrict__ out)
{
    const int cl  = blockIdx.z;
    const int cnt = g_cnt[cl];
    const int m0  = blockIdx.x * TM;
    if (m0 >= cnt) return;
    const int h     = c_h[cl];
    const size_t baseA = c_baseA[cl];
    const size_t baseW = c_baseW[cl];
    const int n0  = blockIdx.y * TN;

    extern __shared__ __align__(16) char smem[];
    const uint32_t sb = smem_u32(smem);
    int* s_tok = (int*)(smem + SM_TOK);

    const int t    = threadIdx.x;
    const int lane = t & 31;
    const int wid  = t >> 5;
    const int wm   = wid & 3;
    const int wn   = wid >> 2;
    const int li   = lane & 7;
    const int sel  = lane >> 3;

    if (t < TM) {
        int m = m0 + t;
        s_tok[t] = (m < cnt) ? g_tok[cl * N_TOK + m] : -1;
    }

    const int nkt = h / TK;
    stage_tiles(sb + SM_A0, sb + SM_B0, t, baseA, baseW, m0, n0, 0, h);
    CP_COMMIT();
    if (nkt > 1) stage_tiles(sb + SM_A1, sb + SM_B1, t, baseA, baseW, m0, n0, TK, h);
    CP_COMMIT();

    float acc[4][4][4];
#pragma unroll
    for (int i = 0; i < 4; i++)
#pragma unroll
        for (int j = 0; j < 4; j++)
#pragma unroll
            for (int q = 0; q < 4; q++) acc[i][j][q] = 0.0f;

    for (int kt = 0; kt < nkt; kt++) {
        CP_WAIT1();
        __syncthreads();
        const uint32_t bA = sb + (((kt & 1) == 0) ? SM_A0 : SM_A1);
        const uint32_t bB = sb + (((kt & 1) == 0) ? SM_B0 : SM_B1);
#pragma unroll
        for (int kh = 0; kh < 2; kh++) {
            const int sh = 2 * kh;
            const int sl = 4 + 2 * kh;
            uint32_t ah[4][4], al[4][4];
#pragma unroll
            for (int mf = 0; mf < 4; mf++) {
                int row = wm * 64 + mf * 16 + li + ((sel & 1) ? 8 : 0);
                ldsm4(ah[mf], bA + sw_off(row, sh + ((sel >> 1) & 1)));
                ldsm4(al[mf], bA + sw_off(row, sl + ((sel >> 1) & 1)));
            }
#pragma unroll
            for (int pp = 0; pp < 2; pp++) {
                int brow = wn * 32 + pp * 16 + li + ((sel >> 1) ? 8 : 0);
                uint32_t bh[4], bl[4];
                ldsm4(bh, bB + sw_off(brow, sh + (sel & 1)));
                ldsm4(bl, bB + sw_off(brow, sl + (sel & 1)));
#pragma unroll
                for (int mf = 0; mf < 4; mf++) {
                    mma_bf16(acc[mf][2 * pp],     ah[mf], bh[0], bh[1]);
                    mma_bf16(acc[mf][2 * pp],     ah[mf], bl[0], bl[1]);
                    mma_bf16(acc[mf][2 * pp],     al[mf], bh[0], bh[1]);
                    mma_bf16(acc[mf][2 * pp + 1], ah[mf], bh[2], bh[3]);
                    mma_bf16(acc[mf][2 * pp + 1], ah[mf], bl[2], bl[3]);
                    mma_bf16(acc[mf][2 * pp + 1], al[mf], bh[2], bh[3]);
                }
            }
        }
        __syncthreads();
        if (kt + 2 < nkt) {
            stage_tiles(bA, bB, t, baseA, baseW, m0, n0, (kt + 2) * TK, h);
        }
        CP_COMMIT();
    }

    const int g  = lane >> 2;
    const int tq = lane & 3;
#pragma unroll
    for (int mf = 0; mf < 4; mf++) {
        int r0 = wm * 64 + mf * 16 + g;
        int tokA = s_tok[r0];
        int tokB = s_tok[r0 + 8];
#pragma unroll
        for (int nf = 0; nf < 4; nf++) {
            int col = n0 + wn * 32 + nf * 8 + tq * 2;
            if (tokA >= 0)
                *(float2*)&out[(size_t)tokA * D_OUT + col] =
                    make_float2(acc[mf][nf][0], acc[mf][nf][1]);
            if (tokB >= 0)
                *(float2*)&out[(size_t)tokB * D_OUT + col] =
                    make_float2(acc[mf][nf][2], acc[mf][nf][3]);
        }
    }
}

extern "C" void kernel_launch(void* const* d_in, const int* in_sizes, int n_in,
                              void* d_out, int out_size)
{
    const void*  idx  = d_in[0];
    const float* emb0 = (const float*)d_in[1];
    const float* w0   = (const float*)d_in[2];
    const float* emb1 = (const float*)d_in[3];
    const float* w1   = (const float*)d_in[4];
    const float* emb2 = (const float*)d_in[5];
    const float* w2   = (const float*)d_in[6];
    float* out = (float*)d_out;

    cudaFuncSetAttribute(gemm_mma, cudaFuncAttributeMaxDynamicSharedMemorySize, SM_TOTAL);

    detect_kernel<<<1, 256>>>((const long long*)idx);
    classify_kernel<<<N_TOK / 256, 256>>>(idx);

    {   // fused weight split: worst-case x for h=1024 is 512 blocks
        dim3 g(512, 1, 3);
        conv_w<<<g, 256>>>(w0, w1, w2);
    }
    {   // fused A split: worst-case x for h=1024, 16384 rows is 8192 blocks
        dim3 g(8192, 1, 3);
        conv_a<<<g, 256>>>(emb0, emb1, emb2);
    }
    {   // fused GEMM across clusters; dead CTAs exit on count check
        dim3 g(N_TOK / TM, D_OUT / TN, 3);
        gemm_mma<<<g, 512, SM_TOTAL>>>(out);
    }
}